// round 9
// baseline (speedup 1.0000x reference)
#include <cuda_runtime.h>
#include <cstdint>

#define B_  256
#define T_  4096
#define I_  63
#define H_  50
#define FC_ 64

#define APPROX_END 4032       // last 64 steps exact tanhf (chunk-aligned)
#define NCHUNK 128            // t-chunks of 32 steps
#define UNITS (B_ * NCHUNK)   // 32768 work units (1 batch-row x 32 timesteps)
#define NCTA 128              // 1 CTA per SM; 2 rnn rows + 2 worker warps each

__device__ float g_xz[(size_t)B_ * T_ * H_ + 4096];
__device__ int g_cnt[NCHUNK];
__device__ unsigned int g_ticket;

// ---------- packed f32x2 helpers ----------
__device__ __forceinline__ unsigned long long pk2(float a, float b) {
    unsigned long long r;
    asm("mov.b64 %0,{%1,%2};" : "=l"(r) : "f"(a), "f"(b));
    return r;
}
__device__ __forceinline__ unsigned long long fma2(unsigned long long a,
                                                   unsigned long long b,
                                                   unsigned long long c) {
    unsigned long long d;
    asm("fma.rn.f32x2 %0,%1,%2,%3;" : "=l"(d) : "l"(a), "l"(b), "l"(c));
    return d;
}
__device__ __forceinline__ unsigned long long add2(unsigned long long a,
                                                   unsigned long long b) {
    unsigned long long d;
    asm("add.rn.f32x2 %0,%1,%2;" : "=l"(d) : "l"(a), "l"(b));
    return d;
}
__device__ __forceinline__ float2 up2(unsigned long long v) {
    float2 r;
    asm("mov.b64 {%0,%1},%2;" : "=f"(r.x), "=f"(r.y) : "l"(v));
    return r;
}
__device__ __forceinline__ float tanh_ap(float x) {
    float y;
    asm("tanh.approx.f32 %0,%1;" : "=f"(y) : "f"(x));
    return y;
}
__device__ __forceinline__ void wait_cnt(int i) {
    int v;
    do {
        asm volatile("ld.acquire.gpu.global.b32 %0, [%1];"
                     : "=r"(v) : "l"(&g_cnt[i]) : "memory");
    } while (v < B_);
}

__global__ void zero_kernel() {
    int t = threadIdx.x;
    if (t < NCHUNK) g_cnt[t] = 0;
    if (t == NCHUNK) g_ticket = 0u;
}

// ========== Fused kernel: 128 CTAs x 128 threads (1 CTA per SM) =============
// warps 2,3: tanh recurrence, rows 2*bid, 2*bid+1  (SMSPs 2,3 — no contention)
// warps 0,1: inproj workers via global ticket      (SMSPs 0,1)
__global__ void __launch_bounds__(128) fused_kernel(
    const float* __restrict__ x,
    const float* __restrict__ W_ih,
    const float* __restrict__ b_ih,
    const float* __restrict__ Whh,
    const float* __restrict__ b_hh,
    const float* __restrict__ W1, const float* __restrict__ b1,
    const float* __restrict__ W2, const float* __restrict__ b2,
    float* __restrict__ out)
{
    __shared__ __align__(8) float Wsh[I_ * H_];        // Wsh[i*50+j]=W_ih[j][i]
    __shared__ __align__(8) float bsh[H_];
    __shared__ __align__(16) float xs[2][32 * I_];     // per-worker-warp slice
    __shared__ __align__(16) unsigned long long hbuf[2][2][32];  // [rnnwarp][buf]

    const int tid  = threadIdx.x;
    const int wid  = tid >> 5;
    const int lane = tid & 31;

    if (wid < 2) {
        // =================== inproj worker role =========================
        for (int idx = lane; idx < I_ * H_; idx += 32) {
            int i = idx / H_, j = idx - i * H_;
            Wsh[idx] = W_ih[j * I_ + i];
        }
        for (int j = lane; j < H_; j += 32) bsh[j] = b_ih[j] + b_hh[j];
        __syncwarp();

        float* myxs = xs[wid];
        for (;;) {
            unsigned u = 0;
            if (lane == 0) u = atomicAdd(&g_ticket, 1u);
            u = __shfl_sync(0xffffffffu, u, 0);
            if (u >= UNITS) break;
            const int tc = (int)(u >> 8);      // t-chunk (increasing order)
            const int b  = (int)(u & 255u);

            // coalesced stage-in: 32 rows x 63 floats = 504 float4
            {
                const float4* s4 = (const float4*)(x + ((size_t)b * T_ + (size_t)tc * 32) * I_);
                float4* d4 = (float4*)myxs;
                for (int i = lane; i < 504; i += 32) d4[i] = s4[i];
            }
            __syncwarp();

            unsigned long long acc[25];
            const float2* bp = (const float2*)bsh;
#pragma unroll
            for (int j2 = 0; j2 < 25; j2++) {
                float2 bv = bp[j2];
                acc[j2] = pk2(bv.x, bv.y);
            }
            const float* xr = myxs + lane * I_;
#pragma unroll 9
            for (int i = 0; i < I_; i++) {
                float xv = xr[i];
                unsigned long long xd = pk2(xv, xv);
                const float2* wrow = (const float2*)(Wsh + i * H_);
#pragma unroll
                for (int j2 = 0; j2 < 25; j2++)
                    acc[j2] = fma2(*(const unsigned long long*)(wrow + j2), xd, acc[j2]);
            }
            __syncwarp();   // x reads done; reuse myxs as out-stage

            float2* orow = (float2*)myxs + lane * 25;
#pragma unroll
            for (int j2 = 0; j2 < 25; j2++) orow[j2] = up2(acc[j2]);
            __syncwarp();

            // coalesced stage-out: 32 rows x 50 floats = 400 float4
            {
                float4* d4 = (float4*)(g_xz + ((size_t)b * T_ + (size_t)tc * 32) * H_);
                const float4* s4 = (const float4*)myxs;
                for (int i = lane; i < 400; i += 32) d4[i] = s4[i];
            }
            __syncwarp();
            if (lane == 0)
                asm volatile("red.release.gpu.global.add.s32 [%0], %1;"
                             :: "l"(&g_cnt[tc]), "r"(1) : "memory");
        }
        return;
    }

    // ================== RNN role (warps 2,3 -> SMSPs 2,3) ===================
    const int rw = wid - 2;                       // 0 or 1
    const int b  = blockIdx.x * 2 + rw;
    const int Lc = (lane < 25) ? lane : 24;       // weight-row clamp only

    unsigned long long w0p[25], w1p[25];
    const float* r0 = Whh + (2 * Lc) * H_;
    const float* r1 = r0 + H_;
#pragma unroll
    for (int k2 = 0; k2 < 25; k2++) {
        w0p[k2] = pk2(__ldg(r0 + 2 * k2), __ldg(r0 + 2 * k2 + 1));
        w1p[k2] = pk2(__ldg(r1 + 2 * k2), __ldg(r1 + 2 * k2 + 1));
    }

    hbuf[rw][0][lane] = 0ull;
    __syncwarp();

    const float* xzp = g_xz + (size_t)b * T_ * H_ + 2 * Lc;

    // wait for chunks 0,1 then prime the depth-4 prefetch ring
    wait_cnt(0);
    wait_cnt(1);
    float2 xr[4];
#pragma unroll
    for (int u = 0; u < 4; u++) xr[u] = *(const float2*)(xzp + u * H_);

#define RNN_STEP(UU, EXACTF) do {                                              \
    const int cb_ = (UU) & 1, nb_ = cb_ ^ 1;                                   \
    float2 xv = xr[UU];                                                        \
    xr[UU] = *(const float2*)(xzp + (size_t)(t + (UU) + 4) * H_);              \
    unsigned long long acc0a = pk2(xv.x, 0.0f);                                \
    unsigned long long acc1a = pk2(xv.y, 0.0f);                                \
    unsigned long long acc0b = 0ull, acc1b = 0ull;                             \
    _Pragma("unroll")                                                          \
    for (int k2 = 0; k2 < 25; k2++) {                                          \
        unsigned long long hk = hbuf[rw][cb_][k2];                             \
        if (k2 & 1) { acc0b = fma2(hk, w0p[k2], acc0b);                        \
                      acc1b = fma2(hk, w1p[k2], acc1b); }                      \
        else        { acc0a = fma2(hk, w0p[k2], acc0a);                        \
                      acc1a = fma2(hk, w1p[k2], acc1a); }                      \
    }                                                                          \
    float2 s0 = up2(add2(acc0a, acc0b));                                       \
    float2 s1 = up2(add2(acc1a, acc1b));                                       \
    float a0 = s0.x + s0.y;                                                    \
    float a1 = s1.x + s1.y;                                                    \
    float h0, h1;                                                              \
    if (EXACTF) { h0 = tanhf(a0);    h1 = tanhf(a1);    }                      \
    else        { h0 = tanh_ap(a0);  h1 = tanh_ap(a1);  }                      \
    hbuf[rw][nb_][lane] = pk2(h0, h1);                                         \
    if (EXACTF) __syncwarp();                                                  \
    else asm volatile("" ::: "memory");  /* converged warp: compiler bar */    \
} while (0)

    for (int tc = 0; tc < NCHUNK; tc++) {
        wait_cnt(tc);
        wait_cnt((tc + 1 < NCHUNK) ? tc + 1 : NCHUNK - 1);
        const int t0 = tc * 32;
        if (t0 < APPROX_END) {
            for (int t = t0; t < t0 + 32; t += 4) {
                RNN_STEP(0, false); RNN_STEP(1, false);
                RNN_STEP(2, false); RNN_STEP(3, false);
            }
        } else {
            for (int t = t0; t < t0 + 32; t += 4) {
                RNN_STEP(0, true); RNN_STEP(1, true);
                RNN_STEP(2, true); RNN_STEP(3, true);
            }
        }
    }
#undef RNN_STEP

    // ---------- MLP head + argmax (final h in hbuf[rw][0][0..24]) ----------
    const float* hf = (const float*)hbuf[rw][0];
    float fc0 = __ldg(b1 + lane);
    float fc1 = __ldg(b1 + lane + 32);
#pragma unroll
    for (int k = 0; k < H_; k++) {
        float hv = hf[k];
        fc0 += hv * __ldg(W1 + lane * H_ + k);
        fc1 += hv * __ldg(W1 + (lane + 32) * H_ + k);
    }
    fc0 = fmaxf(fc0, 0.0f);
    fc1 = fmaxf(fc1, 0.0f);

    float p0 = fc0 * __ldg(W2 + lane)       + fc1 * __ldg(W2 + lane + 32);
    float p1 = fc0 * __ldg(W2 + FC_ + lane) + fc1 * __ldg(W2 + FC_ + lane + 32);
#pragma unroll
    for (int off = 16; off > 0; off >>= 1) {
        p0 += __shfl_xor_sync(0xffffffffu, p0, off);
        p1 += __shfl_xor_sync(0xffffffffu, p1, off);
    }
    if (lane == 0) {
        p0 += __ldg(b2);
        p1 += __ldg(b2 + 1);
        out[b] = (p1 > p0) ? 1.0f : 0.0f;   // argmax; softmax is monotone
    }
}

extern "C" void kernel_launch(void* const* d_in, const int* in_sizes, int n_in,
                              void* d_out, int out_size)
{
    const float* x    = (const float*)d_in[0];
    const float* W_ih = (const float*)d_in[1];
    const float* b_ih = (const float*)d_in[2];
    const float* W_hh = (const float*)d_in[3];
    const float* b_hh = (const float*)d_in[4];
    const float* W1   = (const float*)d_in[5];
    const float* b1   = (const float*)d_in[6];
    const float* W2   = (const float*)d_in[7];
    const float* b2   = (const float*)d_in[8];
    float* out = (float*)d_out;

    zero_kernel<<<1, 160>>>();
    fused_kernel<<<NCTA, 128>>>(x, W_ih, b_ih, W_hh, b_hh, W1, b1, W2, b2, out);
}